// round 2
// baseline (speedup 1.0000x reference)
#include <cuda_runtime.h>
#include <cuda_bf16.h>

// Problem dims
#define B_DIM 128
#define S_DIM 128
#define N_DIM 784          // 28*28
#define D_DIM 512
#define BN_COLS (B_DIM * N_DIM)   // 100352 columns in the big GEMM

// GEMM tile config
#define BN 64
#define BK 32
#define TM 8
#define TN 4
#define GEMM_THREADS 256
#define GEMM_BLOCKS (BN_COLS / BN)   // 1568 exactly

#define GAMMA 10.0f
// EPS: python evaluates 7/3-4/3-1 in double, then casts to float32
#define EPS_F ((float)(7.0/3.0 - 4.0/3.0 - 1.0))   // 2.220446049e-16f
#define Q_MARG (1.0f / (float)N_DIM)
#define P_MARG (1.0f / (float)S_DIM)
#define N_ITERS 10

// Normalized target support (scratch): 128*512 floats = 256 KB
__device__ float g_tn[S_DIM * D_DIM];

// ---------------------------------------------------------------------------
// Kernel 1: normalize target_support rows -> g_tn
// grid = S_DIM blocks, 128 threads; each thread owns one float4 of the row.
// ---------------------------------------------------------------------------
__global__ __launch_bounds__(128) void normT_kernel(const float* __restrict__ t) {
    const int s = blockIdx.x;
    const int tid = threadIdx.x;
    const float4 v = reinterpret_cast<const float4*>(t + s * D_DIM)[tid];
    float sq = v.x * v.x + v.y * v.y + v.z * v.z + v.w * v.w;
    // warp reduce
    #pragma unroll
    for (int m = 16; m > 0; m >>= 1) sq += __shfl_xor_sync(0xffffffffu, sq, m);
    __shared__ float ws[4];
    if ((tid & 31) == 0) ws[tid >> 5] = sq;
    __syncthreads();
    const float tot = ws[0] + ws[1] + ws[2] + ws[3];
    const float r = rsqrtf(tot);
    float4 o;
    o.x = v.x * r; o.y = v.y * r; o.z = v.z * r; o.w = v.w * r;
    reinterpret_cast<float4*>(g_tn + s * D_DIM)[tid] = o;
}

// ---------------------------------------------------------------------------
// Kernel 2: K[b,s,n] = exp(20*cos(t_s, f_bn) - 20), written into d_out.
// Big GEMM: C[s, j] = dot(Tn[s,:], F[j,:]) * rnormF[j], j = b*N + n.
// BM = 128 (covers all S), so grid is only over the 1568 column tiles.
// Feature-row inverse norms are fused into the B-tile loads (each column's
// 512 values are loaded by exactly 4 fixed threads across the k-loop).
// ---------------------------------------------------------------------------
__global__ __launch_bounds__(GEMM_THREADS) void gemm_exp_kernel(
    const float* __restrict__ feat, float* __restrict__ out) {

    __shared__ float As[BK][S_DIM];   // 16 KB, transposed: As[k][s]
    __shared__ float Bs[BK][BN];      //  8 KB, transposed: Bs[k][j]
    __shared__ float rnorm[BN];

    const int tid = threadIdx.x;
    const int tx = tid & 15;          // column group (TN=4 cols)
    const int ty = tid >> 4;          // row group (TM=8 rows)
    const int jBase = blockIdx.x * BN;

    // A-load mapping: thread loads 16 consecutive floats of row sA at dA
    const int sA = tid >> 1;
    const int dA = (tid & 1) * 16;
    // B-load mapping: thread owns column jB, float4 cols cB and cB+1 per tile
    const int jB = tid >> 2;
    const int cB = (2 * tid) & 7;     // in {0,2,4,6}

    const float* featRow = feat + (jBase + jB) * D_DIM;
    const float* aRow = g_tn + sA * D_DIM + dA;

    float acc[TM][TN];
    #pragma unroll
    for (int i = 0; i < TM; i++)
        #pragma unroll
        for (int r = 0; r < TN; r++) acc[i][r] = 0.0f;

    float sq = 0.0f;

    for (int kt = 0; kt < D_DIM; kt += BK) {
        // ---- load A tile (Tn) ----
        const float4* ag = reinterpret_cast<const float4*>(aRow + kt);
        float4 a0 = ag[0], a1 = ag[1], a2 = ag[2], a3 = ag[3];
        As[dA +  0][sA] = a0.x; As[dA +  1][sA] = a0.y;
        As[dA +  2][sA] = a0.z; As[dA +  3][sA] = a0.w;
        As[dA +  4][sA] = a1.x; As[dA +  5][sA] = a1.y;
        As[dA +  6][sA] = a1.z; As[dA +  7][sA] = a1.w;
        As[dA +  8][sA] = a2.x; As[dA +  9][sA] = a2.y;
        As[dA + 10][sA] = a2.z; As[dA + 11][sA] = a2.w;
        As[dA + 12][sA] = a3.x; As[dA + 13][sA] = a3.y;
        As[dA + 14][sA] = a3.z; As[dA + 15][sA] = a3.w;

        // ---- load B tile (raw features) + accumulate sum of squares ----
        const float4* bg = reinterpret_cast<const float4*>(featRow + kt + cB * 4);
        float4 b0 = bg[0], b1 = bg[1];
        sq += b0.x * b0.x + b0.y * b0.y + b0.z * b0.z + b0.w * b0.w;
        sq += b1.x * b1.x + b1.y * b1.y + b1.z * b1.z + b1.w * b1.w;
        const int k0 = cB * 4;
        Bs[k0 + 0][jB] = b0.x; Bs[k0 + 1][jB] = b0.y;
        Bs[k0 + 2][jB] = b0.z; Bs[k0 + 3][jB] = b0.w;
        Bs[k0 + 4][jB] = b1.x; Bs[k0 + 5][jB] = b1.y;
        Bs[k0 + 6][jB] = b1.z; Bs[k0 + 7][jB] = b1.w;

        __syncthreads();

        // ---- compute ----
        #pragma unroll 8
        for (int k = 0; k < BK; k++) {
            float4 aa0 = *reinterpret_cast<const float4*>(&As[k][ty * TM]);
            float4 aa1 = *reinterpret_cast<const float4*>(&As[k][ty * TM + 4]);
            float4 bb  = *reinterpret_cast<const float4*>(&Bs[k][tx * TN]);
            float a[TM] = {aa0.x, aa0.y, aa0.z, aa0.w, aa1.x, aa1.y, aa1.z, aa1.w};
            float b[TN] = {bb.x, bb.y, bb.z, bb.w};
            #pragma unroll
            for (int i = 0; i < TM; i++)
                #pragma unroll
                for (int r = 0; r < TN; r++)
                    acc[i][r] += a[i] * b[r];
        }
        __syncthreads();
    }

    // finish feature-row rnorms: 4 consecutive lanes share column jB
    sq += __shfl_xor_sync(0xffffffffu, sq, 1);
    sq += __shfl_xor_sync(0xffffffffu, sq, 2);
    if ((tid & 3) == 0) rnorm[jB] = rsqrtf(sq);
    __syncthreads();

    // ---- epilogue: cos -> exp, write K into out ----
    const int j0 = jBase + tx * TN;          // 4-aligned; never spans a batch
    const int b  = j0 / N_DIM;
    const int n0 = j0 - b * N_DIM;
    const float rn0 = rnorm[tx * TN + 0];
    const float rn1 = rnorm[tx * TN + 1];
    const float rn2 = rnorm[tx * TN + 2];
    const float rn3 = rnorm[tx * TN + 3];
    float* outB = out + b * (S_DIM * N_DIM) + n0;

    #pragma unroll
    for (int i = 0; i < TM; i++) {
        const int s = ty * TM + i;
        float4 w;
        w.x = __expf(2.0f * GAMMA * (acc[i][0] * rn0) - 2.0f * GAMMA);
        w.y = __expf(2.0f * GAMMA * (acc[i][1] * rn1) - 2.0f * GAMMA);
        w.z = __expf(2.0f * GAMMA * (acc[i][2] * rn2) - 2.0f * GAMMA);
        w.w = __expf(2.0f * GAMMA * (acc[i][3] * rn3) - 2.0f * GAMMA);
        *reinterpret_cast<float4*>(outB + s * N_DIM) = w;
    }
}

// ---------------------------------------------------------------------------
// Kernel 3: Sinkhorn iterations + final Pi scale, in-place on d_out.
// grid = B blocks (one per batch), 512 threads. The 401 KB K-slice per batch
// stays L2-resident across all 21 passes. u (128) and v (784) live in smem.
// ---------------------------------------------------------------------------
__global__ __launch_bounds__(512) void sinkhorn_kernel(float* __restrict__ K) {
    __shared__ float su[S_DIM];
    __shared__ __align__(16) float sv[N_DIM];

    const int tid = threadIdx.x;
    const int lane = tid & 31;
    const int w = tid >> 5;                 // 16 warps
    float* Kb = K + blockIdx.x * (S_DIM * N_DIM);

    if (tid < S_DIM) su[tid] = 1.0f;
    __syncthreads();

    const float4* sv4 = reinterpret_cast<const float4*>(sv);

    for (int it = 0; it <= N_ITERS; it++) {
        // ---- v = q / (u*K + EPS), parallel over n ----
        for (int n = tid; n < N_DIM; n += 512) {
            const float* col = Kb + n;
            float acc = 0.0f;
            #pragma unroll 8
            for (int s = 0; s < S_DIM; s++)
                acc += su[s] * col[s * N_DIM];
            sv[n] = Q_MARG / (acc + EPS_F);
        }
        __syncthreads();
        if (it == N_ITERS) break;           // final v only

        // ---- u = p / (v*K^T + EPS), warp per s-row ----
        for (int s = w; s < S_DIM; s += 16) {
            const float4* row = reinterpret_cast<const float4*>(Kb + s * N_DIM);
            float acc = 0.0f;
            for (int g = lane; g < N_DIM / 4; g += 32) {
                float4 kk = row[g];
                float4 vv = sv4[g];
                acc += kk.x * vv.x + kk.y * vv.y + kk.z * vv.z + kk.w * vv.w;
            }
            #pragma unroll
            for (int m = 16; m > 0; m >>= 1) acc += __shfl_xor_sync(0xffffffffu, acc, m);
            if (lane == 0) su[s] = P_MARG / (acc + EPS_F);
        }
        __syncthreads();
    }
    __syncthreads();

    // ---- Pi = u * K * v, in place ----
    float4* Kb4 = reinterpret_cast<float4*>(Kb);
    const int NG = N_DIM / 4;               // 196 float4 per row
    for (int idx = tid; idx < S_DIM * NG; idx += 512) {
        const int s = idx / NG;
        const int g = idx - s * NG;
        float4 kk = Kb4[idx];
        const float us = su[s];
        const float4 vv = sv4[g];
        kk.x *= us * vv.x;
        kk.y *= us * vv.y;
        kk.z *= us * vv.z;
        kk.w *= us * vv.w;
        Kb4[idx] = kk;
    }
}

// ---------------------------------------------------------------------------
extern "C" void kernel_launch(void* const* d_in, const int* in_sizes, int n_in,
                              void* d_out, int out_size) {
    const float* features;
    const float* target;
    if (in_sizes[0] == S_DIM * D_DIM) {     // robust to input ordering
        target   = (const float*)d_in[0];
        features = (const float*)d_in[1];
    } else {
        features = (const float*)d_in[0];
        target   = (const float*)d_in[1];
    }
    float* out = (float*)d_out;

    normT_kernel<<<S_DIM, 128>>>(target);
    gemm_exp_kernel<<<GEMM_BLOCKS, GEMM_THREADS>>>(features, out);
    sinkhorn_kernel<<<B_DIM, 512>>>(out);
}

// round 8
// speedup vs baseline: 1.4700x; 1.4700x over previous
#include <cuda_runtime.h>
#include <cuda_bf16.h>
#include <cstdint>

// ---------------- problem dims ----------------
#define B_DIM 128
#define S_DIM 128
#define N_DIM 784
#define D_DIM 512
#define BN_COLS (B_DIM * N_DIM)     // 100352

#define GAMMA 10.0f
#define EPS_F ((float)(7.0/3.0 - 4.0/3.0 - 1.0))
#define Q_MARG (1.0f / (float)N_DIM)
#define P_MARG (1.0f / (float)S_DIM)
#define N_ITERS 10

// normalized + tf32-rounded target support
__device__ float g_tn[S_DIM * D_DIM];

// ---------------- helpers ----------------
__device__ __forceinline__ uint32_t smem_u32(const void* p) {
    uint32_t a;
    asm("{ .reg .u64 t; cvta.to.shared.u64 t, %1; cvt.u32.u64 %0, t; }" : "=r"(a) : "l"(p));
    return a;
}
__device__ __forceinline__ void cp16(uint32_t dst, const void* src) {
    asm volatile("cp.async.cg.shared.global [%0], [%1], 16;" :: "r"(dst), "l"(src));
}
#define CP_COMMIT() asm volatile("cp.async.commit_group;" ::: "memory")
#define CP_WAIT1()  asm volatile("cp.async.wait_group 1;" ::: "memory")

__device__ __forceinline__ uint32_t cvt_tf32(float x) {
    uint32_t r;
    asm("cvt.rna.tf32.f32 %0, %1;" : "=r"(r) : "f"(x));
    return r;
}
// D += A*B, m16n8k8 tf32 (standard PTX, works on compute_103)
__device__ __forceinline__ void mma_m16n8k8(float* d, const uint32_t* a,
                                            uint32_t b0, uint32_t b1) {
    asm volatile(
        "mma.sync.aligned.m16n8k8.row.col.f32.tf32.tf32.f32 "
        "{%0,%1,%2,%3}, {%4,%5,%6,%7}, {%8,%9}, {%0,%1,%2,%3};"
        : "+f"(d[0]), "+f"(d[1]), "+f"(d[2]), "+f"(d[3])
        : "r"(a[0]), "r"(a[1]), "r"(a[2]), "r"(a[3]), "r"(b0), "r"(b1));
}

// ---------------- kernel 1: normalize + tf32-round target support ----------------
__global__ __launch_bounds__(128) void normT_kernel(const float* __restrict__ t) {
    const int s = blockIdx.x;
    const int tid = threadIdx.x;
    const float4 v = reinterpret_cast<const float4*>(t + s * D_DIM)[tid];
    float sq = v.x * v.x + v.y * v.y + v.z * v.z + v.w * v.w;
    #pragma unroll
    for (int m = 16; m > 0; m >>= 1) sq += __shfl_xor_sync(0xffffffffu, sq, m);
    __shared__ float ws[4];
    if ((tid & 31) == 0) ws[tid >> 5] = sq;
    __syncthreads();
    const float r = rsqrtf(ws[0] + ws[1] + ws[2] + ws[3]);
    uint4 o;
    o.x = cvt_tf32(v.x * r); o.y = cvt_tf32(v.y * r);
    o.z = cvt_tf32(v.z * r); o.w = cvt_tf32(v.w * r);
    reinterpret_cast<uint4*>(g_tn + s * D_DIM)[tid] = o;
}

// ---------------- kernel 2: mma.sync TF32 GEMM + exp epilogue ----------------
// One CTA: K[:, j0:j0+128]. A = g_tn [128x512] (pre-rounded tf32),
// B = features [100352x512] raw fp32 (cvt in regs). 16 K-chunks of 32.
// smem rows padded to 36 floats -> fragment LDS (addr = 4*gid + tig mod 32)
// is conflict-free without swizzle.
#define ROW_F 36
#define ROW_BYTES (ROW_F * 4)               // 144
#define CHUNK_F (128 * ROW_F)               // 4608 floats
#define CHUNK_BYTES (CHUNK_F * 4)           // 18432
#define NCHUNK 16
#define GEMM_SMEM_BYTES ((4 * CHUNK_F + 128) * 4)   // A x2, B x2, rn

__device__ __forceinline__ void issue_chunk(int c, int jbase, const float* __restrict__ feat,
                                            uint32_t aBase, uint32_t bBase, int tid) {
    if (c < NCHUNK) {
        const int r = tid >> 1;
        const int q4 = (tid & 1) * 4;             // starting float4 within row
        const int k0 = c * 32;
        const uint32_t dOff = (uint32_t)(c & 1) * CHUNK_BYTES + (uint32_t)r * ROW_BYTES + q4 * 16;
        const float* aSrc = g_tn + r * D_DIM + k0 + q4 * 4;
        const float* bSrc = feat + (size_t)(jbase + r) * D_DIM + k0 + q4 * 4;
        #pragma unroll
        for (int i = 0; i < 4; i++) {
            cp16(aBase + dOff + i * 16, aSrc + i * 4);
            cp16(bBase + dOff + i * 16, bSrc + i * 4);
        }
    }
    CP_COMMIT();
}

__global__ __launch_bounds__(256, 2) void gemm_mma_kernel(const float* __restrict__ feat,
                                                          float* __restrict__ out) {
    extern __shared__ float sm[];
    float* Abuf = sm;                       // 2 * CHUNK_F
    float* Bbuf = sm + 2 * CHUNK_F;         // 2 * CHUNK_F
    float* rn   = sm + 4 * CHUNK_F;         // 128
    const uint32_t aBase = smem_u32(Abuf);
    const uint32_t bBase = smem_u32(Bbuf);

    const int tid  = threadIdx.x;
    const int wid  = tid >> 5;
    const int lane = tid & 31;
    const int gid  = lane >> 2;             // group id 0..7
    const int tig  = lane & 3;              // thread-in-group 0..3
    const int mbase = (wid & 3) * 32;       // warp M offset
    const int nbase = (wid >> 2) * 64;      // warp N offset
    const bool doSq = (wid & 3) == 0;
    const int jbase = blockIdx.x * 128;

    float acc[2][8][4];
    #pragma unroll
    for (int mf = 0; mf < 2; mf++)
        #pragma unroll
        for (int nf = 0; nf < 8; nf++)
            #pragma unroll
            for (int r = 0; r < 4; r++) acc[mf][nf][r] = 0.0f;
    float sq[8];
    #pragma unroll
    for (int nf = 0; nf < 8; nf++) sq[nf] = 0.0f;

    issue_chunk(0, jbase, feat, aBase, bBase, tid);

    for (int c = 0; c < NCHUNK; c++) {
        issue_chunk(c + 1, jbase, feat, aBase, bBase, tid);
        CP_WAIT1();
        __syncthreads();

        const uint32_t* Au = (const uint32_t*)(Abuf + (c & 1) * CHUNK_F);
        const float*    Bf = Bbuf + (c & 1) * CHUNK_F;

        #pragma unroll
        for (int ks = 0; ks < 4; ks++) {
            const int k0 = ks * 8;
            uint32_t a[2][4];
            #pragma unroll
            for (int mf = 0; mf < 2; mf++) {
                const int r0 = mbase + mf * 16 + gid;
                a[mf][0] = Au[r0 * ROW_F + k0 + tig];
                a[mf][1] = Au[(r0 + 8) * ROW_F + k0 + tig];
                a[mf][2] = Au[r0 * ROW_F + k0 + tig + 4];
                a[mf][3] = Au[(r0 + 8) * ROW_F + k0 + tig + 4];
            }
            #pragma unroll
            for (int nf = 0; nf < 8; nf++) {
                const int n0 = nbase + nf * 8 + gid;
                const float bf0 = Bf[n0 * ROW_F + k0 + tig];
                const float bf1 = Bf[n0 * ROW_F + k0 + tig + 4];
                if (doSq) {
                    sq[nf] = fmaf(bf0, bf0, sq[nf]);
                    sq[nf] = fmaf(bf1, bf1, sq[nf]);
                }
                const uint32_t b0 = cvt_tf32(bf0);
                const uint32_t b1 = cvt_tf32(bf1);
                mma_m16n8k8(acc[0][nf], a[0], b0, b1);
                mma_m16n8k8(acc[1][nf], a[1], b0, b1);
            }
        }
        __syncthreads();
    }

    // rnorms: each (j,k) raw feature was squared exactly once (Mwarp==0 warps)
    if (doSq) {
        #pragma unroll
        for (int nf = 0; nf < 8; nf++) {
            float s = sq[nf];
            s += __shfl_xor_sync(0xffffffffu, s, 1);
            s += __shfl_xor_sync(0xffffffffu, s, 2);
            if (tig == 0) rn[nbase + nf * 8 + gid] = rsqrtf(s);
        }
    }
    __syncthreads();

    // epilogue: exp(20*cos - 20); c frag cols are pairs (tig*2, tig*2+1)
    #pragma unroll
    for (int mf = 0; mf < 2; mf++) {
        const int s0 = mbase + mf * 16 + gid;
        #pragma unroll
        for (int nf = 0; nf < 8; nf++) {
            const int jj = nbase + nf * 8 + tig * 2;
            const float r0 = rn[jj], r1 = rn[jj + 1];
            const int j = jbase + jj;              // even; pair never crosses batch
            const int b = j / N_DIM;
            const int n = j - b * N_DIM;
            float2 w;
            w.x = __expf(2.0f * GAMMA * (acc[mf][nf][0] * r0) - 2.0f * GAMMA);
            w.y = __expf(2.0f * GAMMA * (acc[mf][nf][1] * r1) - 2.0f * GAMMA);
            *reinterpret_cast<float2*>(out + ((size_t)(b * S_DIM + s0)) * N_DIM + n) = w;
            w.x = __expf(2.0f * GAMMA * (acc[mf][nf][2] * r0) - 2.0f * GAMMA);
            w.y = __expf(2.0f * GAMMA * (acc[mf][nf][3] * r1) - 2.0f * GAMMA);
            *reinterpret_cast<float2*>(out + ((size_t)(b * S_DIM + s0 + 8)) * N_DIM + n) = w;
        }
    }
}

// ---------------- kernel 3: Sinkhorn + Pi scale ----------------
__global__ __launch_bounds__(512) void sinkhorn_kernel(float* __restrict__ K) {
    __shared__ float su[S_DIM];
    __shared__ __align__(16) float sv[N_DIM];

    const int tid = threadIdx.x;
    const int lane = tid & 31;
    const int w = tid >> 5;
    float* Kb = K + blockIdx.x * (S_DIM * N_DIM);

    if (tid < S_DIM) su[tid] = 1.0f;
    __syncthreads();

    const float4* sv4 = reinterpret_cast<const float4*>(sv);

    for (int it = 0; it <= N_ITERS; it++) {
        for (int n = tid; n < N_DIM; n += 512) {
            const float* col = Kb + n;
            float acc = 0.0f;
            #pragma unroll 8
            for (int s = 0; s < S_DIM; s++)
                acc += su[s] * col[s * N_DIM];
            sv[n] = Q_MARG / (acc + EPS_F);
        }
        __syncthreads();
        if (it == N_ITERS) break;

        for (int s = w; s < S_DIM; s += 16) {
            const float4* row = reinterpret_cast<const float4*>(Kb + s * N_DIM);
            float acc = 0.0f;
            for (int g = lane; g < N_DIM / 4; g += 32) {
                float4 kk = row[g];
                float4 vv = sv4[g];
                acc += kk.x * vv.x + kk.y * vv.y + kk.z * vv.z + kk.w * vv.w;
            }
            #pragma unroll
            for (int m = 16; m > 0; m >>= 1) acc += __shfl_xor_sync(0xffffffffu, acc, m);
            if (lane == 0) su[s] = P_MARG / (acc + EPS_F);
        }
        __syncthreads();
    }
    __syncthreads();

    float4* Kb4 = reinterpret_cast<float4*>(Kb);
    const int NG = N_DIM / 4;
    for (int idx = tid; idx < S_DIM * NG; idx += 512) {
        const int s = idx / NG;
        const int g = idx - s * NG;
        float4 kk = Kb4[idx];
        const float us = su[s];
        const float4 vv = sv4[g];
        kk.x *= us * vv.x; kk.y *= us * vv.y;
        kk.z *= us * vv.z; kk.w *= us * vv.w;
        Kb4[idx] = kk;
    }
}

// ---------------- launcher ----------------
extern "C" void kernel_launch(void* const* d_in, const int* in_sizes, int n_in,
                              void* d_out, int out_size) {
    const float* features;
    const float* target;
    if (in_sizes[0] == S_DIM * D_DIM) {
        target   = (const float*)d_in[0];
        features = (const float*)d_in[1];
    } else {
        features = (const float*)d_in[0];
        target   = (const float*)d_in[1];
    }
    float* out = (float*)d_out;

    cudaFuncSetAttribute(gemm_mma_kernel, cudaFuncAttributeMaxDynamicSharedMemorySize,
                         GEMM_SMEM_BYTES);

    normT_kernel<<<S_DIM, 128>>>(target);
    gemm_mma_kernel<<<BN_COLS / 128, 256, GEMM_SMEM_BYTES>>>(features, out);
    sinkhorn_kernel<<<B_DIM, 512>>>(out);
}

// round 17
// speedup vs baseline: 2.4781x; 1.6858x over previous
#include <cuda_runtime.h>
#include <cuda_bf16.h>
#include <cstdint>

// ---------------- problem dims ----------------
#define B_DIM 128
#define S_DIM 128
#define N_DIM 784
#define D_DIM 512
#define BN_COLS (B_DIM * N_DIM)     // 100352

#define GAMMA 10.0f
#define EPS_F ((float)(7.0/3.0 - 4.0/3.0 - 1.0))
#define Q_MARG (1.0f / (float)N_DIM)
#define P_MARG (1.0f / (float)S_DIM)
#define N_ITERS 10

// normalized + tf32-rounded target support
__device__ float g_tn[S_DIM * D_DIM];

// ---------------- helpers ----------------
__device__ __forceinline__ uint32_t smem_u32(const void* p) {
    uint32_t a;
    asm("{ .reg .u64 t; cvta.to.shared.u64 t, %1; cvt.u32.u64 %0, t; }" : "=r"(a) : "l"(p));
    return a;
}
__device__ __forceinline__ void cp16(uint32_t dst, const void* src) {
    asm volatile("cp.async.cg.shared.global [%0], [%1], 16;" :: "r"(dst), "l"(src));
}
#define CP_COMMIT() asm volatile("cp.async.commit_group;" ::: "memory")
#define CP_WAIT1()  asm volatile("cp.async.wait_group 1;" ::: "memory")

__device__ __forceinline__ uint32_t cvt_tf32(float x) {
    uint32_t r;
    asm("cvt.rna.tf32.f32 %0, %1;" : "=r"(r) : "f"(x));
    return r;
}
// D += A*B, m16n8k8 tf32 (standard PTX, works on compute_103)
__device__ __forceinline__ void mma_m16n8k8(float* d, const uint32_t* a,
                                            uint32_t b0, uint32_t b1) {
    asm volatile(
        "mma.sync.aligned.m16n8k8.row.col.f32.tf32.tf32.f32 "
        "{%0,%1,%2,%3}, {%4,%5,%6,%7}, {%8,%9}, {%0,%1,%2,%3};"
        : "+f"(d[0]), "+f"(d[1]), "+f"(d[2]), "+f"(d[3])
        : "r"(a[0]), "r"(a[1]), "r"(a[2]), "r"(a[3]), "r"(b0), "r"(b1));
}

// ---------------- kernel 1: normalize + tf32-round target support ----------------
__global__ __launch_bounds__(128) void normT_kernel(const float* __restrict__ t) {
    const int s = blockIdx.x;
    const int tid = threadIdx.x;
    const float4 v = reinterpret_cast<const float4*>(t + s * D_DIM)[tid];
    float sq = v.x * v.x + v.y * v.y + v.z * v.z + v.w * v.w;
    #pragma unroll
    for (int m = 16; m > 0; m >>= 1) sq += __shfl_xor_sync(0xffffffffu, sq, m);
    __shared__ float ws[4];
    if ((tid & 31) == 0) ws[tid >> 5] = sq;
    __syncthreads();
    const float r = rsqrtf(ws[0] + ws[1] + ws[2] + ws[3]);
    uint4 o;
    o.x = cvt_tf32(v.x * r); o.y = cvt_tf32(v.y * r);
    o.z = cvt_tf32(v.z * r); o.w = cvt_tf32(v.w * r);
    reinterpret_cast<uint4*>(g_tn + s * D_DIM)[tid] = o;
}

// ---------------- kernel 2: mma.sync TF32 GEMM + exp epilogue ----------------
// One CTA: K[:, j0:j0+128]. 512 threads, 16 warps in 4(M) x 4(N) grid,
// warp tile 32x32. smem rows padded to 36 floats -> conflict-free frag LDS.
#define ROW_F 36
#define ROW_BYTES (ROW_F * 4)               // 144
#define CHUNK_F (128 * ROW_F)               // 4608 floats
#define CHUNK_BYTES (CHUNK_F * 4)           // 18432
#define NCHUNK 16
#define GEMM_SMEM_BYTES ((4 * CHUNK_F + 128) * 4)   // A x2, B x2, rn

__device__ __forceinline__ void issue_chunk(int c, int jbase, const float* __restrict__ feat,
                                            uint32_t aBase, uint32_t bBase, int tid) {
    if (c < NCHUNK) {
        const int r  = tid >> 2;                 // row 0..127
        const int q  = (tid & 3) * 2;            // float4 slots q, q+1
        const int k0 = c * 32;
        const uint32_t dOff = (uint32_t)(c & 1) * CHUNK_BYTES + (uint32_t)r * ROW_BYTES + q * 16;
        const float* aSrc = g_tn + r * D_DIM + k0 + q * 4;
        const float* bSrc = feat + (size_t)(jbase + r) * D_DIM + k0 + q * 4;
        cp16(aBase + dOff,      aSrc);
        cp16(aBase + dOff + 16, aSrc + 4);
        cp16(bBase + dOff,      bSrc);
        cp16(bBase + dOff + 16, bSrc + 4);
    }
    CP_COMMIT();
}

__global__ __launch_bounds__(512, 2) void gemm_mma_kernel(const float* __restrict__ feat,
                                                          float* __restrict__ out) {
    extern __shared__ float sm[];
    float* Abuf = sm;                       // 2 * CHUNK_F
    float* Bbuf = sm + 2 * CHUNK_F;         // 2 * CHUNK_F
    float* rn   = sm + 4 * CHUNK_F;         // 128
    const uint32_t aBase = smem_u32(Abuf);
    const uint32_t bBase = smem_u32(Bbuf);

    const int tid  = threadIdx.x;
    const int wid  = tid >> 5;
    const int lane = tid & 31;
    const int gid  = lane >> 2;             // 0..7
    const int tig  = lane & 3;              // 0..3
    const int mbase = (wid & 3) * 32;       // M warp offset
    const int nbase = (wid >> 2) * 32;      // N warp offset
    const bool doSq = (wid & 3) == 0;       // 4 warps cover all 128 cols once
    const int jbase = blockIdx.x * 128;

    float acc[2][4][4];
    #pragma unroll
    for (int mf = 0; mf < 2; mf++)
        #pragma unroll
        for (int nf = 0; nf < 4; nf++)
            #pragma unroll
            for (int r = 0; r < 4; r++) acc[mf][nf][r] = 0.0f;
    float sq[4] = {0.0f, 0.0f, 0.0f, 0.0f};

    issue_chunk(0, jbase, feat, aBase, bBase, tid);

    for (int c = 0; c < NCHUNK; c++) {
        issue_chunk(c + 1, jbase, feat, aBase, bBase, tid);
        CP_WAIT1();
        __syncthreads();

        const uint32_t* Au = (const uint32_t*)(Abuf + (c & 1) * CHUNK_F);
        const float*    Bf = Bbuf + (c & 1) * CHUNK_F;

        #pragma unroll
        for (int ks = 0; ks < 4; ks++) {
            const int k0 = ks * 8;
            uint32_t a[2][4];
            #pragma unroll
            for (int mf = 0; mf < 2; mf++) {
                const int r0 = mbase + mf * 16 + gid;
                a[mf][0] = Au[r0 * ROW_F + k0 + tig];
                a[mf][1] = Au[(r0 + 8) * ROW_F + k0 + tig];
                a[mf][2] = Au[r0 * ROW_F + k0 + tig + 4];
                a[mf][3] = Au[(r0 + 8) * ROW_F + k0 + tig + 4];
            }
            #pragma unroll
            for (int nf = 0; nf < 4; nf++) {
                const int n0 = nbase + nf * 8 + gid;
                const float bf0 = Bf[n0 * ROW_F + k0 + tig];
                const float bf1 = Bf[n0 * ROW_F + k0 + tig + 4];
                if (doSq) {
                    sq[nf] = fmaf(bf0, bf0, sq[nf]);
                    sq[nf] = fmaf(bf1, bf1, sq[nf]);
                }
                const uint32_t b0 = cvt_tf32(bf0);
                const uint32_t b1 = cvt_tf32(bf1);
                mma_m16n8k8(acc[0][nf], a[0], b0, b1);
                mma_m16n8k8(acc[1][nf], a[1], b0, b1);
            }
        }
        __syncthreads();
    }

    // rnorms: each (j,k) squared exactly once (mwarp==0 warps)
    if (doSq) {
        #pragma unroll
        for (int nf = 0; nf < 4; nf++) {
            float s = sq[nf];
            s += __shfl_xor_sync(0xffffffffu, s, 1);
            s += __shfl_xor_sync(0xffffffffu, s, 2);
            if (tig == 0) rn[nbase + nf * 8 + gid] = rsqrtf(s);
        }
    }
    __syncthreads();

    // epilogue: exp(20*cos - 20); c frag cols are pairs (tig*2, tig*2+1)
    #pragma unroll
    for (int mf = 0; mf < 2; mf++) {
        const int s0 = mbase + mf * 16 + gid;
        #pragma unroll
        for (int nf = 0; nf < 4; nf++) {
            const int jj = nbase + nf * 8 + tig * 2;
            const float r0 = rn[jj], r1 = rn[jj + 1];
            const int j = jbase + jj;              // even; pair never crosses batch
            const int b = j / N_DIM;
            const int n = j - b * N_DIM;
            float2 w;
            w.x = __expf(2.0f * GAMMA * (acc[mf][nf][0] * r0) - 2.0f * GAMMA);
            w.y = __expf(2.0f * GAMMA * (acc[mf][nf][1] * r1) - 2.0f * GAMMA);
            *reinterpret_cast<float2*>(out + ((size_t)(b * S_DIM + s0)) * N_DIM + n) = w;
            w.x = __expf(2.0f * GAMMA * (acc[mf][nf][2] * r0) - 2.0f * GAMMA);
            w.y = __expf(2.0f * GAMMA * (acc[mf][nf][3] * r1) - 2.0f * GAMMA);
            *reinterpret_cast<float2*>(out + ((size_t)(b * S_DIM + s0 + 8)) * N_DIM + n) = w;
        }
    }
}

// ---------------- kernel 3: Sinkhorn, rows 0..63 cached in smem ----------------
#define SROWS 64
#define NG (N_DIM / 4)                       // 196 float4 per row
#define SINK_SMEM_F (SROWS * N_DIM + N_DIM + S_DIM)
#define SINK_SMEM_BYTES (SINK_SMEM_F * 4)    // 204352

__global__ __launch_bounds__(512) void sinkhorn_kernel(float* __restrict__ K) {
    extern __shared__ float sm[];
    float* Ks = sm;                          // 64*784
    float* sv = sm + SROWS * N_DIM;          // 784 (16B aligned)
    float* su = sv + N_DIM;                  // 128

    const int tid  = threadIdx.x;
    const int lane = tid & 31;
    const int w    = tid >> 5;               // 16 warps
    float* Kb = K + (size_t)blockIdx.x * (S_DIM * N_DIM);
    float* Kg = Kb + SROWS * N_DIM;          // global rows 64..127

    float4*       Ks4  = reinterpret_cast<float4*>(Ks);
    const float4* Kb4c = reinterpret_cast<const float4*>(Kb);
    const float4* Kg4c = reinterpret_cast<const float4*>(Kg);
    const float4* sv4  = reinterpret_cast<const float4*>(sv);

    // load rows 0..63 into smem
    for (int idx = tid; idx < SROWS * NG; idx += 512) Ks4[idx] = Kb4c[idx];
    if (tid < S_DIM) su[tid] = 1.0f;
    __syncthreads();

    for (int it = 0; it <= N_ITERS; it++) {
        // ---- v-step: colsum over all 128 rows ----
        for (int n = tid; n < N_DIM; n += 512) {
            float accg = 0.0f;
            const float* colg = Kg + n;      // global half first (latency)
            #pragma unroll 8
            for (int s = 0; s < SROWS; s++)
                accg += su[SROWS + s] * colg[s * N_DIM];
            float accs = 0.0f;
            #pragma unroll 8
            for (int s = 0; s < SROWS; s++)
                accs += su[s] * Ks[s * N_DIM + n];
            sv[n] = Q_MARG / (accs + accg + EPS_F);
        }
        __syncthreads();
        if (it == N_ITERS) break;

        // ---- u-step: warp w handles smem rows 4w..4w+3 and global rows 64+4w..64+4w+3 ----
        {
            const int r0 = 4 * w;
            float as[4] = {0, 0, 0, 0};
            float ag[4] = {0, 0, 0, 0};
            for (int g = lane; g < NG; g += 32) {
                const float4 vv = sv4[g];
                #pragma unroll
                for (int r = 0; r < 4; r++) {
                    const float4 kk = Ks4[(r0 + r) * NG + g];
                    as[r] += kk.x * vv.x + kk.y * vv.y + kk.z * vv.z + kk.w * vv.w;
                }
                #pragma unroll
                for (int r = 0; r < 4; r++) {
                    const float4 kk = Kg4c[(r0 + r) * NG + g];
                    ag[r] += kk.x * vv.x + kk.y * vv.y + kk.z * vv.z + kk.w * vv.w;
                }
            }
            // full-warp butterfly: every lane ends with the complete sums
            #pragma unroll
            for (int r = 0; r < 4; r++) {
                #pragma unroll
                for (int m = 16; m > 0; m >>= 1) {
                    as[r] += __shfl_xor_sync(0xffffffffu, as[r], m);
                    ag[r] += __shfl_xor_sync(0xffffffffu, ag[r], m);
                }
            }
            if (lane == 0) {                  // no divergent shfl: write directly
                #pragma unroll
                for (int r = 0; r < 4; r++) {
                    su[r0 + r]         = P_MARG / (as[r] + EPS_F);
                    su[SROWS + r0 + r] = P_MARG / (ag[r] + EPS_F);
                }
            }
        }
        __syncthreads();
    }
    __syncthreads();

    // ---- Pi = u * K * v ----
    float4* Kb4 = reinterpret_cast<float4*>(Kb);
    float4* Kg4 = reinterpret_cast<float4*>(Kg);
    for (int idx = tid; idx < SROWS * NG; idx += 512) {
        const int s = idx / NG;
        const int g = idx - s * NG;
        float4 kk = Ks4[idx];
        const float us = su[s];
        const float4 vv = sv4[g];
        kk.x *= us * vv.x; kk.y *= us * vv.y;
        kk.z *= us * vv.z; kk.w *= us * vv.w;
        Kb4[idx] = kk;
    }
    for (int idx = tid; idx < SROWS * NG; idx += 512) {
        const int s = idx / NG;
        const int g = idx - s * NG;
        float4 kk = Kg4[idx];
        const float us = su[SROWS + s];
        const float4 vv = sv4[g];
        kk.x *= us * vv.x; kk.y *= us * vv.y;
        kk.z *= us * vv.z; kk.w *= us * vv.w;
        Kg4[idx] = kk;
    }
}

// ---------------- launcher ----------------
extern "C" void kernel_launch(void* const* d_in, const int* in_sizes, int n_in,
                              void* d_out, int out_size) {
    const float* features;
    const float* target;
    if (in_sizes[0] == S_DIM * D_DIM) {
        target   = (const float*)d_in[0];
        features = (const float*)d_in[1];
    } else {
        features = (const float*)d_in[0];
        target   = (const float*)d_in[1];
    }
    float* out = (float*)d_out;

    cudaFuncSetAttribute(gemm_mma_kernel, cudaFuncAttributeMaxDynamicSharedMemorySize,
                         GEMM_SMEM_BYTES);
    cudaFuncSetAttribute(sinkhorn_kernel, cudaFuncAttributeMaxDynamicSharedMemorySize,
                         SINK_SMEM_BYTES);

    normT_kernel<<<S_DIM, 128>>>(target);
    gemm_mma_kernel<<<BN_COLS / 128, 512, GEMM_SMEM_BYTES>>>(features, out);
    sinkhorn_kernel<<<B_DIM, 512, SINK_SMEM_BYTES>>>(out);
}